// round 16
// baseline (speedup 1.0000x reference)
#include <cuda_runtime.h>
#include <cuda_fp16.h>
#include <math.h>
#include <stdint.h>

#define D_BATCH   4
#define N_SEQ     4096
#define NTOK      (D_BATCH * N_SEQ)
#define DMODEL    1024
#define HALF      512
#define HDQK      512
#define HDV       512
#define FF_DIM    2048
#define NBUCKETS  64
#define CHUNK     128
#define NCHUNKS   128
#define PENALTY_INV (1.0f / 100000.0f)
#define LN_EPS    1e-5f

// scratch
__device__ __half g_qkvh [NTOK * 1024];
__device__ __half g_attnh[NTOK * HDV];
__device__ __half g_x2h  [NTOK * HALF];
__device__ __half g_y1h  [NTOK * HALF];
__device__ __half g_hb   [NTOK * FF_DIM];
__device__ __half g_uh   [NTOK * HALF];
__device__ __half g_fh   [NTOK * HALF];
__device__ __half g_WTh  [1024 * HALF];
__device__ __half g_uTh  [HALF * HDV];
__device__ __half g_ff1Th[FF_DIM * HALF];
__device__ __half g_ff2Th[HALF * FF_DIM];
__device__ float  g_bqkv [1024];
__device__ float  g_M    [HALF * 32];
__device__ float  g_pb   [32];
__device__ int    g_hash [NTOK];
__device__ int    g_rank [NTOK];
__device__ int    g_cnt  [D_BATCH * NBUCKETS * 32];
__device__ int    g_idx  [NTOK];

// ---- helpers ----
__device__ __forceinline__ uint32_t smem_u32(const void* p) {
    uint32_t a;
    asm("{ .reg .u64 t; cvta.to.shared.u64 t, %1; cvt.u32.u64 %0, t; }"
        : "=r"(a) : "l"(p));
    return a;
}
__device__ __forceinline__ void cp16(uint32_t dst, const void* src) {
    asm volatile("cp.async.cg.shared.global [%0], [%1], 16;" :: "r"(dst), "l"(src));
}
template <int N> __device__ __forceinline__ void cp_wait() {
    asm volatile("cp.async.wait_group %0;" :: "n"(N) : "memory");
}
#define CP_COMMIT() asm volatile("cp.async.commit_group;" ::: "memory")

// fp16 mma m16n8k16, fp32 accumulate
__device__ __forceinline__ void mma16(float* c, const uint32_t* a, const uint32_t* b) {
    asm volatile("mma.sync.aligned.m16n8k16.row.col.f32.f16.f16.f32 "
                 "{%0,%1,%2,%3}, {%4,%5,%6,%7}, {%8,%9}, {%0,%1,%2,%3};"
                 : "+f"(c[0]), "+f"(c[1]), "+f"(c[2]), "+f"(c[3])
                 : "r"(a[0]), "r"(a[1]), "r"(a[2]), "r"(a[3]),
                   "r"(b[0]), "r"(b[1]));
}

// ldmatrix x4 (b16)
__device__ __forceinline__ void ldsm4(uint32_t* r, uint32_t addr) {
    asm volatile("ldmatrix.sync.aligned.m8n8.x4.shared.b16 {%0,%1,%2,%3}, [%4];"
                 : "=r"(r[0]), "=r"(r[1]), "=r"(r[2]), "=r"(r[3]) : "r"(addr));
}

// ---------------------------------------------------------------------------
// fp16 mma.sync GEMM, 3-stage cp.async pipeline, ldmatrix fragment loads.
// CTA 128x128, BK=64 halves, 128 thr = 4 warps (2x2), warp tile 64x64.
// ---------------------------------------------------------------------------
#define ASTR  72
#define STG_H (128 * ASTR)
#define GK_SMEM (3 * 2 * STG_H * 2)

template <int RELU, int OUTH>
__global__ __launch_bounds__(128, 2)
void gemm_mma(const __half* __restrict__ A, int lda,
              const __half* __restrict__ Bt,
              const float* __restrict__ bias,
              void* __restrict__ Cv, int ldc, int K)
{
    extern __shared__ __half smh[];
    const int tid  = threadIdx.x;
    const int wid  = tid >> 5;
    const int lane = tid & 31;
    const int gid  = lane >> 2;
    const int tig  = lane & 3;
    const int warp_m = (wid >> 1) * 64;
    const int warp_n = (wid & 1) * 64;
    const int bm = blockIdx.x * 128;
    const int bn = blockIdx.y * 128;
    const int nk = K / 64;

    uint32_t sbase = smem_u32(smh);

    const uint32_t a_lane = ((warp_m + (lane & 15)) * ASTR + (lane >> 4) * 8) * 2;
    const uint32_t b_lane = ((warp_n + (lane & 7) + ((lane >> 4) << 3)) * ASTR
                             + ((lane >> 3) & 1) * 8) * 2;

    auto load_stage = [&](int st, int kc) {
        const int k0 = kc * 64;
        uint32_t sa = sbase + st * (2 * STG_H * 2);
        uint32_t sb = sa + STG_H * 2;
#pragma unroll
        for (int i = 0; i < 8; i++) {
            int idx = i * 128 + tid;
            int row = idx >> 3, c8 = idx & 7;
            cp16(sa + (row * ASTR + c8 * 8) * 2,
                 A + (size_t)(bm + row) * lda + k0 + c8 * 8);
            cp16(sb + (row * ASTR + c8 * 8) * 2,
                 Bt + (size_t)(bn + row) * K + k0 + c8 * 8);
        }
        CP_COMMIT();
    };

    float acc[4][8][4];
#pragma unroll
    for (int mt = 0; mt < 4; mt++)
#pragma unroll
        for (int nt = 0; nt < 8; nt++)
#pragma unroll
            for (int e = 0; e < 4; e++) acc[mt][nt][e] = 0.f;

    load_stage(0, 0);
    load_stage(1, 1);

    for (int kc = 0; kc < nk; kc++) {
        if (kc == nk - 1) cp_wait<0>(); else cp_wait<1>();
        __syncthreads();
        if (kc + 2 < nk) load_stage((kc + 2) % 3, kc + 2);
        uint32_t a_base = sbase + (kc % 3) * (2 * STG_H * 2) + a_lane;
        uint32_t b_base = sbase + (kc % 3) * (2 * STG_H * 2) + STG_H * 2 + b_lane;
#pragma unroll
        for (int ks = 0; ks < 4; ks++) {
            uint32_t af[4][4], bf[8][2];
#pragma unroll
            for (int mt = 0; mt < 4; mt++)
                ldsm4(af[mt], a_base + mt * (16 * ASTR * 2) + ks * 32);
#pragma unroll
            for (int j = 0; j < 4; j++) {
                uint32_t r[4];
                ldsm4(r, b_base + j * (16 * ASTR * 2) + ks * 32);
                bf[2 * j][0] = r[0]; bf[2 * j][1] = r[1];
                bf[2 * j + 1][0] = r[2]; bf[2 * j + 1][1] = r[3];
            }
#pragma unroll
            for (int mt = 0; mt < 4; mt++)
#pragma unroll
                for (int nt = 0; nt < 8; nt++)
                    mma16(acc[mt][nt], af[mt], bf[nt]);
        }
    }

#pragma unroll
    for (int mt = 0; mt < 4; mt++) {
        int r0 = bm + warp_m + mt * 16 + gid;
#pragma unroll
        for (int nt = 0; nt < 8; nt++) {
            int c = bn + warp_n + nt * 8 + 2 * tig;
            float b0 = bias[c], b1 = bias[c + 1];
            float v0 = acc[mt][nt][0] + b0, v1 = acc[mt][nt][1] + b1;
            float v2 = acc[mt][nt][2] + b0, v3 = acc[mt][nt][3] + b1;
            if (RELU) {
                v0 = fmaxf(v0, 0.f); v1 = fmaxf(v1, 0.f);
                v2 = fmaxf(v2, 0.f); v3 = fmaxf(v3, 0.f);
            }
            if (OUTH) {
                __half* Ch = (__half*)Cv;
                *(__half2*)(Ch + (size_t)r0 * ldc + c) = __floats2half2_rn(v0, v1);
                *(__half2*)(Ch + (size_t)(r0 + 8) * ldc + c) = __floats2half2_rn(v2, v3);
            } else {
                float* Cf = (float*)Cv;
                float2 p0 = {v0, v1}, p1 = {v2, v3};
                *(float2*)(Cf + (size_t)r0 * ldc + c) = p0;
                *(float2*)(Cf + (size_t)(r0 + 8) * ldc + c) = p1;
            }
        }
    }
}

// ---------------------------------------------------------------------------
// fp16 tensor-core LSH attention; cb0 = chunk offset for split launches.
// ---------------------------------------------------------------------------
#define SSTH 136
#define AT_SMEM ((128 * SSTH + 3 * 128 * ASTR) * 2)

__global__ __launch_bounds__(256, 1)
void attn_mma(const __half* __restrict__ qkv, const int* __restrict__ idx,
              __half* __restrict__ attn, int cb0)
{
    extern __shared__ __half smh[];
    __half* sS = smh;
    __half* sQ = smh + 128 * SSTH;
    __shared__ int stok[CHUNK];

    const int cb = blockIdx.x + cb0;
    const int b = cb >> 5;
    const int tid = threadIdx.x;
    const int wid = tid >> 5;
    const int lane = tid & 31;
    const int gid = lane >> 2;
    const int tig = lane & 3;
    const int warp_m = (wid >> 2) * 64;
    const int warp_n = (wid & 3) * 32;

    if (tid < CHUNK)
        stok[tid] = (b * N_SEQ + idx[cb * CHUNK + tid]) * 1024;
    __syncthreads();

    uint32_t sqbase = smem_u32(sQ);

    auto loadQ = [&](int st, int kc) {
#pragma unroll
        for (int i = 0; i < 4; i++) {
            int u = i * 256 + tid;
            int row = u >> 3, c8 = u & 7;
            cp16(sqbase + (st * 128 * ASTR + row * ASTR + c8 * 8) * 2,
                 qkv + stok[row] + kc * 64 + c8 * 8);
        }
        CP_COMMIT();
    };

    float acc[4][4][4];
#pragma unroll
    for (int mt = 0; mt < 4; mt++)
#pragma unroll
        for (int nt = 0; nt < 4; nt++)
#pragma unroll
            for (int e = 0; e < 4; e++) acc[mt][nt][e] = 0.f;

    loadQ(0, 0);
    loadQ(1, 1);
    for (int kc = 0; kc < 8; kc++) {
        if (kc == 7) cp_wait<0>(); else cp_wait<1>();
        __syncthreads();
        if (kc + 2 < 8) loadQ((kc + 2) % 3, kc + 2);
        const __half* sA = sQ + (kc % 3) * 128 * ASTR;
#pragma unroll
        for (int ks = 0; ks < 4; ks++) {
            uint32_t af[4][4], bf[4][2];
#pragma unroll
            for (int mt = 0; mt < 4; mt++) {
                const __half* ap = sA + (warp_m + mt * 16 + gid) * ASTR + ks * 16 + tig * 2;
                af[mt][0] = *(const uint32_t*)(ap);
                af[mt][1] = *(const uint32_t*)(ap + 8 * ASTR);
                af[mt][2] = *(const uint32_t*)(ap + 8);
                af[mt][3] = *(const uint32_t*)(ap + 8 * ASTR + 8);
            }
#pragma unroll
            for (int nt = 0; nt < 4; nt++) {
                const __half* bp = sA + (warp_n + nt * 8 + gid) * ASTR + ks * 16 + tig * 2;
                bf[nt][0] = *(const uint32_t*)(bp);
                bf[nt][1] = *(const uint32_t*)(bp + 8);
            }
#pragma unroll
            for (int mt = 0; mt < 4; mt++)
#pragma unroll
                for (int nt = 0; nt < 4; nt++)
                    mma16(acc[mt][nt], af[mt], bf[nt]);
        }
    }
    __syncthreads();

#pragma unroll
    for (int mt = 0; mt < 4; mt++) {
        int r = warp_m + mt * 16 + gid;
#pragma unroll
        for (int nt = 0; nt < 4; nt++) {
            int c = warp_n + nt * 8 + 2 * tig;
            float v0 = acc[mt][nt][0] * 0.125f;
            float v1 = acc[mt][nt][1] * 0.125f;
            float v2 = acc[mt][nt][2] * 0.125f;
            float v3 = acc[mt][nt][3] * 0.125f;
            if (r == c) v0 *= PENALTY_INV;
            if (r == c + 1) v1 *= PENALTY_INV;
            if (r + 8 == c) v2 *= PENALTY_INV;
            if (r + 8 == c + 1) v3 *= PENALTY_INV;
            *(__half2*)(sS + r * SSTH + c) = __floats2half2_rn(v0, v1);
            *(__half2*)(sS + (r + 8) * SSTH + c) = __floats2half2_rn(v2, v3);
        }
    }
    __syncthreads();

    __half* sVt = sQ;
    __half* orow = attn + (size_t)(cb * CHUNK) * HDV;

    for (int ntile = 0; ntile < 4; ntile++) {
#pragma unroll
        for (int mt = 0; mt < 4; mt++)
#pragma unroll
            for (int nt = 0; nt < 4; nt++)
#pragma unroll
                for (int e = 0; e < 4; e++) acc[mt][nt][e] = 0.f;

        uint4 vreg[2];
        auto ldV = [&](int kc) {
            int tok = stok[kc * 32 + lane];
#pragma unroll
            for (int u = 0; u < 2; u++) {
                int nq = u * 8 + wid;
                vreg[u] = *(const uint4*)(qkv + tok + 512 + ntile * 128 + nq * 8);
            }
        };
        ldV(0);
        for (int kc = 0; kc < 4; kc++) {
#pragma unroll
            for (int u = 0; u < 2; u++) {
                int n0 = (u * 8 + wid) * 8;
                const __half* hv = (const __half*)&vreg[u];
#pragma unroll
                for (int e = 0; e < 8; e++)
                    sVt[(n0 + e) * ASTR + lane] = hv[e];
            }
            __syncthreads();
            if (kc < 3) ldV(kc + 1);
#pragma unroll
            for (int ks = 0; ks < 2; ks++) {
                uint32_t af[4][4], bf[4][2];
                int kk = kc * 32 + ks * 16 + tig * 2;
#pragma unroll
                for (int mt = 0; mt < 4; mt++) {
                    const __half* ap = sS + (warp_m + mt * 16 + gid) * SSTH + kk;
                    af[mt][0] = *(const uint32_t*)(ap);
                    af[mt][1] = *(const uint32_t*)(ap + 8 * SSTH);
                    af[mt][2] = *(const uint32_t*)(ap + 8);
                    af[mt][3] = *(const uint32_t*)(ap + 8 * SSTH + 8);
                }
#pragma unroll
                for (int nt = 0; nt < 4; nt++) {
                    const __half* bp = sVt + (warp_n + nt * 8 + gid) * ASTR + ks * 16 + tig * 2;
                    bf[nt][0] = *(const uint32_t*)(bp);
                    bf[nt][1] = *(const uint32_t*)(bp + 8);
                }
#pragma unroll
                for (int mt = 0; mt < 4; mt++)
#pragma unroll
                    for (int nt = 0; nt < 4; nt++)
                        mma16(acc[mt][nt], af[mt], bf[nt]);
            }
            __syncthreads();
        }

#pragma unroll
        for (int mt = 0; mt < 4; mt++) {
            int r0 = warp_m + mt * 16 + gid;
#pragma unroll
            for (int nt = 0; nt < 4; nt++) {
                int c = ntile * 128 + warp_n + nt * 8 + 2 * tig;
                *(__half2*)(orow + (size_t)r0 * HDV + c) =
                    __floats2half2_rn(acc[mt][nt][0], acc[mt][nt][1]);
                *(__half2*)(orow + (size_t)(r0 + 8) * HDV + c) =
                    __floats2half2_rn(acc[mt][nt][2], acc[mt][nt][3]);
            }
        }
    }
}

// ---- prep kernels ----
__global__ __launch_bounds__(256)
void cvt_x2_kernel(const float* __restrict__ x, __half* __restrict__ x2h)
{
    size_t i = (size_t)blockIdx.x * 256 + threadIdx.x;
    int t = (int)(i >> 7), g = (int)(i & 127);
    float4 v = *(const float4*)(x + (size_t)t * DMODEL + HALF + g * 4);
    __half2 h0 = __floats2half2_rn(v.x, v.y);
    __half2 h1 = __floats2half2_rn(v.z, v.w);
    *(__half2*)(x2h + (size_t)t * HALF + g * 4) = h0;
    *(__half2*)(x2h + (size_t)t * HALF + g * 4 + 2) = h1;
}

// weight transposes (fp32 -> fp16), dispatched by block id + offset
__global__ __launch_bounds__(256)
void transpose_some(int id_off,
                    const float* __restrict__ w0, __half* __restrict__ t0,
                    const float* __restrict__ w1, __half* __restrict__ t1,
                    const float* __restrict__ w2, __half* __restrict__ t2,
                    const float* __restrict__ w3, __half* __restrict__ t3,
                    const float* __restrict__ w4, __half* __restrict__ t4)
{
    __shared__ float tile[32][33];
    int id = blockIdx.x + id_off;
    const float* W; __half* Wt; int K, N, local;
    if (id < 256)       { W = w0; Wt = t0; K = 512;  N = 512;  local = id; }
    else if (id < 512)  { W = w1; Wt = t1; K = 512;  N = 512;  local = id - 256; }
    else if (id < 768)  { W = w2; Wt = t2; K = 512;  N = 512;  local = id - 512; }
    else if (id < 1792) { W = w3; Wt = t3; K = 512;  N = 2048; local = id - 768; }
    else                { W = w4; Wt = t4; K = 2048; N = 512;  local = id - 1792; }
    int nbx = N / 32;
    int bx = (local % nbx) * 32;
    int by = (local / nbx) * 32;
    int tx = threadIdx.x & 31, ty = (threadIdx.x >> 5) * 4;
#pragma unroll
    for (int i = 0; i < 4; i++)
        tile[ty + i][tx] = W[(size_t)(by + ty + i) * N + bx + tx];
    __syncthreads();
#pragma unroll
    for (int i = 0; i < 4; i++)
        Wt[(size_t)(bx + ty + i) * K + by + tx] = __float2half_rn(tile[tx][ty + i]);
}

__global__ __launch_bounds__(256)
void bias_cat_kernel(const float* __restrict__ b0, const float* __restrict__ b1,
                     float* __restrict__ bo)
{
    int i = blockIdx.x * 256 + threadIdx.x;
    if (i < 512) bo[i] = b0[i];
    else if (i < 1024) bo[i] = b1[i - 512];
}

// fused hash projection, split-K: 4 warps per output row + smem reduce.
__global__ __launch_bounds__(256)
void hashM_kernel(const float* __restrict__ W, const float* __restrict__ bvec,
                  const float* __restrict__ H, float* __restrict__ M,
                  float* __restrict__ pb)
{
    __shared__ float part[8][32];
    int wid = threadIdx.x >> 5, j = threadIdx.x & 31;
    int row = blockIdx.x * 2 + (wid >> 2);
    int q = wid & 3;
    const float* src = (row < HALF) ? (W + (size_t)row * HDQK)
                     : ((row == HALF) ? bvec : nullptr);
    float s0 = 0.f, s1 = 0.f, s2 = 0.f, s3 = 0.f;
    if (src) {
        int c0 = q * 128;
#pragma unroll 8
        for (int c = c0; c < c0 + 128; c += 4) {
            float4 w = *(const float4*)(src + c);
            s0 = fmaf(w.x, H[(c + 0) * 32 + j], s0);
            s1 = fmaf(w.y, H[(c + 1) * 32 + j], s1);
            s2 = fmaf(w.z, H[(c + 2) * 32 + j], s2);
            s3 = fmaf(w.w, H[(c + 3) * 32 + j], s3);
        }
    }
    part[wid][j] = (s0 + s1) + (s2 + s3);
    __syncthreads();
    if ((wid & 3) == 0) {
        float s = part[wid][j] + part[wid + 1][j] + part[wid + 2][j] + part[wid + 3][j];
        if (row < HALF) M[row * 32 + j] = s;
        else if (row == HALF) pb[j] = s;
    }
}

// hash from raw x (exact fp32): one warp per token, 4-way ILP
__global__ __launch_bounds__(256)
void hash_kernel(const float* __restrict__ x, const float* __restrict__ M,
                 const float* __restrict__ pb, int* __restrict__ hashes)
{
    int warp = (blockIdx.x * blockDim.x + threadIdx.x) >> 5;
    int lane = threadIdx.x & 31;
    if (warp >= NTOK) return;
    const float* row = x + (size_t)warp * DMODEL + HALF;
    float s0 = pb[lane], s1 = 0.f, s2 = 0.f, s3 = 0.f;
#pragma unroll 4
    for (int k = 0; k < HALF; k += 4) {
        float4 q = *(const float4*)(row + k);
        s0 = fmaf(q.x, M[(k + 0) * 32 + lane], s0);
        s1 = fmaf(q.y, M[(k + 1) * 32 + lane], s1);
        s2 = fmaf(q.z, M[(k + 2) * 32 + lane], s2);
        s3 = fmaf(q.w, M[(k + 3) * 32 + lane], s3);
    }
    float s = (s0 + s1) + (s2 + s3);
    float val; int idx;
    if (s >= -s) { val = s; idx = lane; }
    else         { val = -s; idx = lane + 32; }
#pragma unroll
    for (int off = 16; off; off >>= 1) {
        float ov = __shfl_down_sync(0xffffffffu, val, off);
        int   oi = __shfl_down_sync(0xffffffffu, idx, off);
        if (ov > val || (ov == val && oi < idx)) { val = ov; idx = oi; }
    }
    if (lane == 0) hashes[warp] = idx;
}

// ---- parallel stable counting sort (2-phase) ----
__global__ __launch_bounds__(128)
void sort1_kernel(const int* __restrict__ hashes, int* __restrict__ rank,
                  int* __restrict__ cnt)
{
    __shared__ int sh[128];
    __shared__ int hist[NBUCKETS];
    int b = blockIdx.x >> 5, ch = blockIdx.x & 31;
    int t = threadIdx.x;
    if (t < NBUCKETS) hist[t] = 0;
    int h = hashes[b * N_SEQ + ch * 128 + t];
    sh[t] = h;
    __syncthreads();
    int r = 0;
    for (int j = 0; j < t; j++) r += (sh[j] == h);
    atomicAdd(&hist[h], 1);
    rank[b * N_SEQ + ch * 128 + t] = r;
    __syncthreads();
    if (t < NBUCKETS) cnt[(b * NBUCKETS + t) * 32 + ch] = hist[t];
}

__global__ __launch_bounds__(1024)
void sort2_kernel(const int* __restrict__ hashes, const int* __restrict__ rank,
                  const int* __restrict__ cnt, int* __restrict__ idx)
{
    __shared__ int off[2048];
    __shared__ int wsum[32];
    int b = blockIdx.x, t = threadIdx.x;
    int lane = t & 31, wid = t >> 5;
    int v0 = cnt[b * 2048 + 2 * t];
    int v1 = cnt[b * 2048 + 2 * t + 1];
    int s = v0 + v1;
    int p = s;
#pragma unroll
    for (int o = 1; o < 32; o <<= 1) {
        int n = __shfl_up_sync(0xffffffffu, p, o);
        if (lane >= o) p += n;
    }
    if (lane == 31) wsum[wid] = p;
    __syncthreads();
    if (wid == 0) {
        int ws = wsum[lane];
#pragma unroll
        for (int o = 1; o < 32; o <<= 1) {
            int n = __shfl_up_sync(0xffffffffu, ws, o);
            if (lane >= o) ws += n;
        }
        wsum[lane] = ws;
    }
    __syncthreads();
    int excl = p - s + (wid ? wsum[wid - 1] : 0);
    off[2 * t] = excl;
    off[2 * t + 1] = excl + v0;
    __syncthreads();
    int* outp = idx + b * N_SEQ;
    const int* hp = hashes + b * N_SEQ;
    const int* rp = rank + b * N_SEQ;
#pragma unroll
    for (int q = 0; q < 4; q++) {
        int i = q * 1024 + t;
        int h = hp[i];
        int r = rp[i];
        int ch = i >> 7;
        outp[off[h * 32 + ch] + r] = i;
    }
}

// residual + LayerNorm; res is half. Optional extra half copy.
__global__ __launch_bounds__(256)
void ln_kernel(const float* __restrict__ x, int xoff,
               const __half* __restrict__ res,
               const float* __restrict__ g, const float* __restrict__ bta,
               float* __restrict__ out, int ooff,
               __half* __restrict__ extra)
{
    __shared__ float red[16];
    int t = blockIdx.x;
    int c0 = threadIdx.x, c1 = threadIdx.x + 256;
    float v0 = x[(size_t)t * DMODEL + xoff + c0] + __half2float(res[(size_t)t * HALF + c0]);
    float v1 = x[(size_t)t * DMODEL + xoff + c1] + __half2float(res[(size_t)t * HALF + c1]);
    float s = v0 + v1, sq = v0 * v0 + v1 * v1;
    int lane = threadIdx.x & 31, wid = threadIdx.x >> 5;
#pragma unroll
    for (int o = 16; o; o >>= 1) {
        s  += __shfl_down_sync(0xffffffffu, s, o);
        sq += __shfl_down_sync(0xffffffffu, sq, o);
    }
    if (lane == 0) { red[wid] = s; red[8 + wid] = sq; }
    __syncthreads();
    if (threadIdx.x < 32) {
        float ss = (lane < 8) ? red[lane] : 0.f;
        float qq = (lane < 8) ? red[8 + lane] : 0.f;
#pragma unroll
        for (int o = 4; o; o >>= 1) {
            ss += __shfl_down_sync(0xffffffffu, ss, o);
            qq += __shfl_down_sync(0xffffffffu, qq, o);
        }
        if (lane == 0) { red[0] = ss; red[8] = qq; }
    }
    __syncthreads();
    float mu = red[0] * (1.f / HALF);
    float var = red[8] * (1.f / HALF) - mu * mu;
    float inv = rsqrtf(var + LN_EPS);
    float o0 = (v0 - mu) * inv * g[c0] + bta[c0];
    float o1 = (v1 - mu) * inv * g[c1] + bta[c1];
    out[(size_t)t * DMODEL + ooff + c0] = o0;
    out[(size_t)t * DMODEL + ooff + c1] = o1;
    if (extra) {
        extra[(size_t)t * HALF + c0] = __float2half_rn(o0);
        extra[(size_t)t * HALF + c1] = __float2half_rn(o1);
    }
}

// ---------------------------------------------------------------------------
extern "C" void kernel_launch(void* const* d_in, const int* in_sizes, int n_in,
                              void* d_out, int out_size)
{
    const float* x       = (const float*)d_in[0];
    const float* Wqk_w   = (const float*)d_in[1];
    const float* Wqk_b   = (const float*)d_in[2];
    const float* Wv_w    = (const float*)d_in[3];
    const float* Wv_b    = (const float*)d_in[4];
    const float* unify_w = (const float*)d_in[5];
    const float* unify_b = (const float*)d_in[6];
    const float* H       = (const float*)d_in[7];
    const float* ln1_g   = (const float*)d_in[8];
    const float* ln1_b   = (const float*)d_in[9];
    const float* ff1_w   = (const float*)d_in[10];
    const float* ff1_b   = (const float*)d_in[11];
    const float* ff2_w   = (const float*)d_in[12];
    const float* ff2_b   = (const float*)d_in[13];
    const float* ln2_g   = (const float*)d_in[14];
    const float* ln2_b   = (const float*)d_in[15];
    float* out = (float*)d_out;

    __half *qkvh, *attnh, *x2h, *y1h, *hb, *uh, *fh, *WTh, *uTh, *ff1Th, *ff2Th;
    float *bqkv, *Mm, *pb;
    int *hashp, *rankp, *cntp, *idxp;
    cudaGetSymbolAddress((void**)&qkvh, g_qkvh);
    cudaGetSymbolAddress((void**)&attnh,g_attnh);
    cudaGetSymbolAddress((void**)&x2h,  g_x2h);
    cudaGetSymbolAddress((void**)&y1h,  g_y1h);
    cudaGetSymbolAddress((void**)&hb,   g_hb);
    cudaGetSymbolAddress((void**)&uh,   g_uh);
    cudaGetSymbolAddress((void**)&fh,   g_fh);
    cudaGetSymbolAddress((void**)&WTh,  g_WTh);
    cudaGetSymbolAddress((void**)&uTh,  g_uTh);
    cudaGetSymbolAddress((void**)&ff1Th,g_ff1Th);
    cudaGetSymbolAddress((void**)&ff2Th,g_ff2Th);
    cudaGetSymbolAddress((void**)&bqkv, g_bqkv);
    cudaGetSymbolAddress((void**)&Mm,   g_M);
    cudaGetSymbolAddress((void**)&pb,   g_pb);
    cudaGetSymbolAddress((void**)&hashp,g_hash);
    cudaGetSymbolAddress((void**)&rankp,g_rank);
    cudaGetSymbolAddress((void**)&cntp, g_cnt);
    cudaGetSymbolAddress((void**)&idxp, g_idx);

    cudaFuncSetAttribute(gemm_mma<0,1>, cudaFuncAttributeMaxDynamicSharedMemorySize, GK_SMEM);
    cudaFuncSetAttribute(gemm_mma<1,1>, cudaFuncAttributeMaxDynamicSharedMemorySize, GK_SMEM);
    cudaFuncSetAttribute(attn_mma, cudaFuncAttributeMaxDynamicSharedMemorySize, AT_SMEM);

    // side stream (created per call; no frees, no device allocations)
    cudaStream_t s1;
    cudaStreamCreateWithFlags(&s1, cudaStreamNonBlocking);
    cudaEvent_t evF, evX, evJ, evA, evU;
    cudaEventCreateWithFlags(&evF, cudaEventDisableTiming);
    cudaEventCreateWithFlags(&evX, cudaEventDisableTiming);
    cudaEventCreateWithFlags(&evJ, cudaEventDisableTiming);
    cudaEventCreateWithFlags(&evA, cudaEventDisableTiming);
    cudaEventCreateWithFlags(&evU, cudaEventDisableTiming);

    cudaEventRecord(evF, 0);
    cudaStreamWaitEvent(s1, evF, 0);

    // side stream: x2 conversion (gates qkv GEMM via evX), then the hash
    // chain, then the remaining weight transposes (all gated by evJ)
    cvt_x2_kernel<<<NTOK * 128 / 256, 256, 0, s1>>>(x, x2h);
    cudaEventRecord(evX, s1);
    hashM_kernel<<<257, 256, 0, s1>>>(Wqk_w, Wqk_b, H, Mm, pb);
    hash_kernel<<<NTOK / 8, 256, 0, s1>>>(x, Mm, pb, hashp);
    sort1_kernel<<<D_BATCH * 32, 128, 0, s1>>>(hashp, rankp, cntp);
    sort2_kernel<<<D_BATCH, 1024, 0, s1>>>(hashp, rankp, cntp, idxp);
    transpose_some<<<2304, 256, 0, s1>>>(512, Wqk_w, WTh, Wv_w, WTh + 512 * 512,
                                         unify_w, uTh, ff1_w, ff1Th, ff2_w, ff2Th);
    cudaEventRecord(evJ, s1);

    // main stream: qk|v weight transpose runs concurrently with cvt_x2
    transpose_some<<<512, 256>>>(0, Wqk_w, WTh, Wv_w, WTh + 512 * 512,
                                 unify_w, uTh, ff1_w, ff1Th, ff2_w, ff2Th);
    bias_cat_kernel<<<4, 256>>>(Wqk_b, Wv_b, bqkv);
    cudaStreamWaitEvent(0, evX, 0);
    gemm_mma<0,1><<<dim3(NTOK / 128, 1024 / 128), 128, GK_SMEM>>>(
        x2h, HALF, WTh, bqkv, qkvh, 1024, HALF);

    cudaStreamWaitEvent(0, evJ, 0);

    // attention split: first half releases unifyA on the side stream
    attn_mma<<<64, 256, AT_SMEM>>>(qkvh, idxp, attnh, 0);
    cudaEventRecord(evA, 0);
    attn_mma<<<64, 256, AT_SMEM>>>(qkvh, idxp, attnh, 64);

    cudaStreamWaitEvent(s1, evA, 0);
    gemm_mma<0,1><<<dim3(64, HALF / 128), 128, GK_SMEM, s1>>>(
        attnh, HDV, uTh, unify_b, uh, HALF, HDV);
    cudaEventRecord(evU, s1);

    gemm_mma<0,1><<<dim3(64, HALF / 128), 128, GK_SMEM>>>(
        attnh + (size_t)8192 * HDV, HDV, uTh, unify_b,
        uh + (size_t)8192 * HALF, HALF, HDV);
    cudaStreamWaitEvent(0, evU, 0);

    // y1 = LN(x1 + u)
    ln_kernel<<<NTOK, 256>>>(x, 0, uh, ln1_g, ln1_b, out, 0, y1h);

    // ff
    gemm_mma<1,1><<<dim3(NTOK / 128, FF_DIM / 128), 128, GK_SMEM>>>(
        y1h, HALF, ff1Th, ff1_b, hb, FF_DIM, HALF);
    gemm_mma<0,1><<<dim3(NTOK / 128, HALF / 128), 128, GK_SMEM>>>(
        hb, FF_DIM, ff2Th, ff2_b, fh, HALF, FF_DIM);

    // y2 = LN(x2 + ff)
    ln_kernel<<<NTOK, 256>>>(x, HALF, fh, ln2_g, ln2_b, out, HALF, nullptr);
}

// round 17
// speedup vs baseline: 1.0650x; 1.0650x over previous
#include <cuda_runtime.h>
#include <cuda_fp16.h>
#include <math.h>
#include <stdint.h>

#define D_BATCH   4
#define N_SEQ     4096
#define NTOK      (D_BATCH * N_SEQ)
#define DMODEL    1024
#define HALF      512
#define HDQK      512
#define HDV       512
#define FF_DIM    2048
#define NBUCKETS  64
#define CHUNK     128
#define NCHUNKS   128
#define PENALTY_INV (1.0f / 100000.0f)
#define LN_EPS    1e-5f

// scratch
__device__ __half g_qkvh [NTOK * 1024];
__device__ __half g_attnh[NTOK * HDV];
__device__ __half g_x2h  [NTOK * HALF];
__device__ __half g_y1h  [NTOK * HALF];
__device__ __half g_hb   [NTOK * FF_DIM];
__device__ __half g_uh   [NTOK * HALF];
__device__ __half g_fh   [NTOK * HALF];
__device__ __half g_WTh  [1024 * HALF];
__device__ __half g_uTh  [HALF * HDV];
__device__ __half g_ff1Th[FF_DIM * HALF];
__device__ __half g_ff2Th[HALF * FF_DIM];
__device__ float  g_bqkv [1024];
__device__ float  g_M    [HALF * 32];
__device__ float  g_pb   [32];
__device__ int    g_hash [NTOK];
__device__ int    g_rank [NTOK];
__device__ int    g_cnt  [D_BATCH * NBUCKETS * 32];
__device__ int    g_idx  [NTOK];

// ---- helpers ----
__device__ __forceinline__ uint32_t smem_u32(const void* p) {
    uint32_t a;
    asm("{ .reg .u64 t; cvta.to.shared.u64 t, %1; cvt.u32.u64 %0, t; }"
        : "=r"(a) : "l"(p));
    return a;
}
__device__ __forceinline__ void cp16(uint32_t dst, const void* src) {
    asm volatile("cp.async.cg.shared.global [%0], [%1], 16;" :: "r"(dst), "l"(src));
}
template <int N> __device__ __forceinline__ void cp_wait() {
    asm volatile("cp.async.wait_group %0;" :: "n"(N) : "memory");
}
#define CP_COMMIT() asm volatile("cp.async.commit_group;" ::: "memory")

// fp16 mma m16n8k16, fp32 accumulate
__device__ __forceinline__ void mma16(float* c, const uint32_t* a, const uint32_t* b) {
    asm volatile("mma.sync.aligned.m16n8k16.row.col.f32.f16.f16.f32 "
                 "{%0,%1,%2,%3}, {%4,%5,%6,%7}, {%8,%9}, {%0,%1,%2,%3};"
                 : "+f"(c[0]), "+f"(c[1]), "+f"(c[2]), "+f"(c[3])
                 : "r"(a[0]), "r"(a[1]), "r"(a[2]), "r"(a[3]),
                   "r"(b[0]), "r"(b[1]));
}

// ldmatrix x4 (b16)
__device__ __forceinline__ void ldsm4(uint32_t* r, uint32_t addr) {
    asm volatile("ldmatrix.sync.aligned.m8n8.x4.shared.b16 {%0,%1,%2,%3}, [%4];"
                 : "=r"(r[0]), "=r"(r[1]), "=r"(r[2]), "=r"(r[3]) : "r"(addr));
}

// ---------------------------------------------------------------------------
// fp16 mma.sync GEMM, 3-stage cp.async pipeline, ldmatrix fragment loads.
// CTA 128x128, BK=64 halves, 128 thr = 4 warps (2x2), warp tile 64x64.
// ---------------------------------------------------------------------------
#define ASTR  72
#define STG_H (128 * ASTR)
#define GK_SMEM (3 * 2 * STG_H * 2)

template <int RELU, int OUTH>
__global__ __launch_bounds__(128, 2)
void gemm_mma(const __half* __restrict__ A, int lda,
              const __half* __restrict__ Bt,
              const float* __restrict__ bias,
              void* __restrict__ Cv, int ldc, int K)
{
    extern __shared__ __half smh[];
    const int tid  = threadIdx.x;
    const int wid  = tid >> 5;
    const int lane = tid & 31;
    const int gid  = lane >> 2;
    const int tig  = lane & 3;
    const int warp_m = (wid >> 1) * 64;
    const int warp_n = (wid & 1) * 64;
    const int bm = blockIdx.x * 128;
    const int bn = blockIdx.y * 128;
    const int nk = K / 64;

    uint32_t sbase = smem_u32(smh);

    const uint32_t a_lane = ((warp_m + (lane & 15)) * ASTR + (lane >> 4) * 8) * 2;
    const uint32_t b_lane = ((warp_n + (lane & 7) + ((lane >> 4) << 3)) * ASTR
                             + ((lane >> 3) & 1) * 8) * 2;

    auto load_stage = [&](int st, int kc) {
        const int k0 = kc * 64;
        uint32_t sa = sbase + st * (2 * STG_H * 2);
        uint32_t sb = sa + STG_H * 2;
#pragma unroll
        for (int i = 0; i < 8; i++) {
            int idx = i * 128 + tid;
            int row = idx >> 3, c8 = idx & 7;
            cp16(sa + (row * ASTR + c8 * 8) * 2,
                 A + (size_t)(bm + row) * lda + k0 + c8 * 8);
            cp16(sb + (row * ASTR + c8 * 8) * 2,
                 Bt + (size_t)(bn + row) * K + k0 + c8 * 8);
        }
        CP_COMMIT();
    };

    float acc[4][8][4];
#pragma unroll
    for (int mt = 0; mt < 4; mt++)
#pragma unroll
        for (int nt = 0; nt < 8; nt++)
#pragma unroll
            for (int e = 0; e < 4; e++) acc[mt][nt][e] = 0.f;

    load_stage(0, 0);
    load_stage(1, 1);

    for (int kc = 0; kc < nk; kc++) {
        if (kc == nk - 1) cp_wait<0>(); else cp_wait<1>();
        __syncthreads();
        if (kc + 2 < nk) load_stage((kc + 2) % 3, kc + 2);
        uint32_t a_base = sbase + (kc % 3) * (2 * STG_H * 2) + a_lane;
        uint32_t b_base = sbase + (kc % 3) * (2 * STG_H * 2) + STG_H * 2 + b_lane;
#pragma unroll
        for (int ks = 0; ks < 4; ks++) {
            uint32_t af[4][4], bf[8][2];
#pragma unroll
            for (int mt = 0; mt < 4; mt++)
                ldsm4(af[mt], a_base + mt * (16 * ASTR * 2) + ks * 32);
#pragma unroll
            for (int j = 0; j < 4; j++) {
                uint32_t r[4];
                ldsm4(r, b_base + j * (16 * ASTR * 2) + ks * 32);
                bf[2 * j][0] = r[0]; bf[2 * j][1] = r[1];
                bf[2 * j + 1][0] = r[2]; bf[2 * j + 1][1] = r[3];
            }
#pragma unroll
            for (int mt = 0; mt < 4; mt++)
#pragma unroll
                for (int nt = 0; nt < 8; nt++)
                    mma16(acc[mt][nt], af[mt], bf[nt]);
        }
    }

#pragma unroll
    for (int mt = 0; mt < 4; mt++) {
        int r0 = bm + warp_m + mt * 16 + gid;
#pragma unroll
        for (int nt = 0; nt < 8; nt++) {
            int c = bn + warp_n + nt * 8 + 2 * tig;
            float b0 = bias[c], b1 = bias[c + 1];
            float v0 = acc[mt][nt][0] + b0, v1 = acc[mt][nt][1] + b1;
            float v2 = acc[mt][nt][2] + b0, v3 = acc[mt][nt][3] + b1;
            if (RELU) {
                v0 = fmaxf(v0, 0.f); v1 = fmaxf(v1, 0.f);
                v2 = fmaxf(v2, 0.f); v3 = fmaxf(v3, 0.f);
            }
            if (OUTH) {
                __half* Ch = (__half*)Cv;
                *(__half2*)(Ch + (size_t)r0 * ldc + c) = __floats2half2_rn(v0, v1);
                *(__half2*)(Ch + (size_t)(r0 + 8) * ldc + c) = __floats2half2_rn(v2, v3);
            } else {
                float* Cf = (float*)Cv;
                float2 p0 = {v0, v1}, p1 = {v2, v3};
                *(float2*)(Cf + (size_t)r0 * ldc + c) = p0;
                *(float2*)(Cf + (size_t)(r0 + 8) * ldc + c) = p1;
            }
        }
    }
}

// ---------------------------------------------------------------------------
// fp16 tensor-core LSH attention (single 128-CTA launch, R14 config).
// ---------------------------------------------------------------------------
#define SSTH 136
#define AT_SMEM ((128 * SSTH + 3 * 128 * ASTR) * 2)

__global__ __launch_bounds__(256, 1)
void attn_mma(const __half* __restrict__ qkv, const int* __restrict__ idx,
              __half* __restrict__ attn)
{
    extern __shared__ __half smh[];
    __half* sS = smh;
    __half* sQ = smh + 128 * SSTH;
    __shared__ int stok[CHUNK];

    const int cb = blockIdx.x;
    const int b = cb >> 5;
    const int tid = threadIdx.x;
    const int wid = tid >> 5;
    const int lane = tid & 31;
    const int gid = lane >> 2;
    const int tig = lane & 3;
    const int warp_m = (wid >> 2) * 64;
    const int warp_n = (wid & 3) * 32;

    if (tid < CHUNK)
        stok[tid] = (b * N_SEQ + idx[cb * CHUNK + tid]) * 1024;
    __syncthreads();

    uint32_t sqbase = smem_u32(sQ);

    auto loadQ = [&](int st, int kc) {
#pragma unroll
        for (int i = 0; i < 4; i++) {
            int u = i * 256 + tid;
            int row = u >> 3, c8 = u & 7;
            cp16(sqbase + (st * 128 * ASTR + row * ASTR + c8 * 8) * 2,
                 qkv + stok[row] + kc * 64 + c8 * 8);
        }
        CP_COMMIT();
    };

    float acc[4][4][4];
#pragma unroll
    for (int mt = 0; mt < 4; mt++)
#pragma unroll
        for (int nt = 0; nt < 4; nt++)
#pragma unroll
            for (int e = 0; e < 4; e++) acc[mt][nt][e] = 0.f;

    loadQ(0, 0);
    loadQ(1, 1);
    for (int kc = 0; kc < 8; kc++) {
        if (kc == 7) cp_wait<0>(); else cp_wait<1>();
        __syncthreads();
        if (kc + 2 < 8) loadQ((kc + 2) % 3, kc + 2);
        const __half* sA = sQ + (kc % 3) * 128 * ASTR;
#pragma unroll
        for (int ks = 0; ks < 4; ks++) {
            uint32_t af[4][4], bf[4][2];
#pragma unroll
            for (int mt = 0; mt < 4; mt++) {
                const __half* ap = sA + (warp_m + mt * 16 + gid) * ASTR + ks * 16 + tig * 2;
                af[mt][0] = *(const uint32_t*)(ap);
                af[mt][1] = *(const uint32_t*)(ap + 8 * ASTR);
                af[mt][2] = *(const uint32_t*)(ap + 8);
                af[mt][3] = *(const uint32_t*)(ap + 8 * ASTR + 8);
            }
#pragma unroll
            for (int nt = 0; nt < 4; nt++) {
                const __half* bp = sA + (warp_n + nt * 8 + gid) * ASTR + ks * 16 + tig * 2;
                bf[nt][0] = *(const uint32_t*)(bp);
                bf[nt][1] = *(const uint32_t*)(bp + 8);
            }
#pragma unroll
            for (int mt = 0; mt < 4; mt++)
#pragma unroll
                for (int nt = 0; nt < 4; nt++)
                    mma16(acc[mt][nt], af[mt], bf[nt]);
        }
    }
    __syncthreads();

#pragma unroll
    for (int mt = 0; mt < 4; mt++) {
        int r = warp_m + mt * 16 + gid;
#pragma unroll
        for (int nt = 0; nt < 4; nt++) {
            int c = warp_n + nt * 8 + 2 * tig;
            float v0 = acc[mt][nt][0] * 0.125f;
            float v1 = acc[mt][nt][1] * 0.125f;
            float v2 = acc[mt][nt][2] * 0.125f;
            float v3 = acc[mt][nt][3] * 0.125f;
            if (r == c) v0 *= PENALTY_INV;
            if (r == c + 1) v1 *= PENALTY_INV;
            if (r + 8 == c) v2 *= PENALTY_INV;
            if (r + 8 == c + 1) v3 *= PENALTY_INV;
            *(__half2*)(sS + r * SSTH + c) = __floats2half2_rn(v0, v1);
            *(__half2*)(sS + (r + 8) * SSTH + c) = __floats2half2_rn(v2, v3);
        }
    }
    __syncthreads();

    __half* sVt = sQ;
    __half* orow = attn + (size_t)(cb * CHUNK) * HDV;

    for (int ntile = 0; ntile < 4; ntile++) {
#pragma unroll
        for (int mt = 0; mt < 4; mt++)
#pragma unroll
            for (int nt = 0; nt < 4; nt++)
#pragma unroll
                for (int e = 0; e < 4; e++) acc[mt][nt][e] = 0.f;

        uint4 vreg[2];
        auto ldV = [&](int kc) {
            int tok = stok[kc * 32 + lane];
#pragma unroll
            for (int u = 0; u < 2; u++) {
                int nq = u * 8 + wid;
                vreg[u] = *(const uint4*)(qkv + tok + 512 + ntile * 128 + nq * 8);
            }
        };
        ldV(0);
        for (int kc = 0; kc < 4; kc++) {
#pragma unroll
            for (int u = 0; u < 2; u++) {
                int n0 = (u * 8 + wid) * 8;
                const __half* hv = (const __half*)&vreg[u];
#pragma unroll
                for (int e = 0; e < 8; e++)
                    sVt[(n0 + e) * ASTR + lane] = hv[e];
            }
            __syncthreads();
            if (kc < 3) ldV(kc + 1);
#pragma unroll
            for (int ks = 0; ks < 2; ks++) {
                uint32_t af[4][4], bf[4][2];
                int kk = kc * 32 + ks * 16 + tig * 2;
#pragma unroll
                for (int mt = 0; mt < 4; mt++) {
                    const __half* ap = sS + (warp_m + mt * 16 + gid) * SSTH + kk;
                    af[mt][0] = *(const uint32_t*)(ap);
                    af[mt][1] = *(const uint32_t*)(ap + 8 * SSTH);
                    af[mt][2] = *(const uint32_t*)(ap + 8);
                    af[mt][3] = *(const uint32_t*)(ap + 8 * SSTH + 8);
                }
#pragma unroll
                for (int nt = 0; nt < 4; nt++) {
                    const __half* bp = sVt + (warp_n + nt * 8 + gid) * ASTR + ks * 16 + tig * 2;
                    bf[nt][0] = *(const uint32_t*)(bp);
                    bf[nt][1] = *(const uint32_t*)(bp + 8);
                }
#pragma unroll
                for (int mt = 0; mt < 4; mt++)
#pragma unroll
                    for (int nt = 0; nt < 4; nt++)
                        mma16(acc[mt][nt], af[mt], bf[nt]);
            }
            __syncthreads();
        }

#pragma unroll
        for (int mt = 0; mt < 4; mt++) {
            int r0 = warp_m + mt * 16 + gid;
#pragma unroll
            for (int nt = 0; nt < 4; nt++) {
                int c = ntile * 128 + warp_n + nt * 8 + 2 * tig;
                *(__half2*)(orow + (size_t)r0 * HDV + c) =
                    __floats2half2_rn(acc[mt][nt][0], acc[mt][nt][1]);
                *(__half2*)(orow + (size_t)(r0 + 8) * HDV + c) =
                    __floats2half2_rn(acc[mt][nt][2], acc[mt][nt][3]);
            }
        }
    }
}

// ---- prep kernels ----
__global__ __launch_bounds__(256)
void cvt_x2_kernel(const float* __restrict__ x, __half* __restrict__ x2h)
{
    size_t i = (size_t)blockIdx.x * 256 + threadIdx.x;
    int t = (int)(i >> 7), g = (int)(i & 127);
    float4 v = *(const float4*)(x + (size_t)t * DMODEL + HALF + g * 4);
    __half2 h0 = __floats2half2_rn(v.x, v.y);
    __half2 h1 = __floats2half2_rn(v.z, v.w);
    *(__half2*)(x2h + (size_t)t * HALF + g * 4) = h0;
    *(__half2*)(x2h + (size_t)t * HALF + g * 4 + 2) = h1;
}

// weight transposes (fp32 -> fp16), dispatched by block id + offset
__global__ __launch_bounds__(256)
void transpose_some(int id_off,
                    const float* __restrict__ w0, __half* __restrict__ t0,
                    const float* __restrict__ w1, __half* __restrict__ t1,
                    const float* __restrict__ w2, __half* __restrict__ t2,
                    const float* __restrict__ w3, __half* __restrict__ t3,
                    const float* __restrict__ w4, __half* __restrict__ t4)
{
    __shared__ float tile[32][33];
    int id = blockIdx.x + id_off;
    const float* W; __half* Wt; int K, N, local;
    if (id < 256)       { W = w0; Wt = t0; K = 512;  N = 512;  local = id; }
    else if (id < 512)  { W = w1; Wt = t1; K = 512;  N = 512;  local = id - 256; }
    else if (id < 768)  { W = w2; Wt = t2; K = 512;  N = 512;  local = id - 512; }
    else if (id < 1792) { W = w3; Wt = t3; K = 512;  N = 2048; local = id - 768; }
    else                { W = w4; Wt = t4; K = 2048; N = 512;  local = id - 1792; }
    int nbx = N / 32;
    int bx = (local % nbx) * 32;
    int by = (local / nbx) * 32;
    int tx = threadIdx.x & 31, ty = (threadIdx.x >> 5) * 4;
#pragma unroll
    for (int i = 0; i < 4; i++)
        tile[ty + i][tx] = W[(size_t)(by + ty + i) * N + bx + tx];
    __syncthreads();
#pragma unroll
    for (int i = 0; i < 4; i++)
        Wt[(size_t)(bx + ty + i) * K + by + tx] = __float2half_rn(tile[tx][ty + i]);
}

__global__ __launch_bounds__(256)
void bias_cat_kernel(const float* __restrict__ b0, const float* __restrict__ b1,
                     float* __restrict__ bo)
{
    int i = blockIdx.x * 256 + threadIdx.x;
    if (i < 512) bo[i] = b0[i];
    else if (i < 1024) bo[i] = b1[i - 512];
}

// fused hash projection, split-K: 4 warps per output row + smem reduce.
__global__ __launch_bounds__(256)
void hashM_kernel(const float* __restrict__ W, const float* __restrict__ bvec,
                  const float* __restrict__ H, float* __restrict__ M,
                  float* __restrict__ pb)
{
    __shared__ float part[8][32];
    int wid = threadIdx.x >> 5, j = threadIdx.x & 31;
    int row = blockIdx.x * 2 + (wid >> 2);
    int q = wid & 3;
    const float* src = (row < HALF) ? (W + (size_t)row * HDQK)
                     : ((row == HALF) ? bvec : nullptr);
    float s0 = 0.f, s1 = 0.f, s2 = 0.f, s3 = 0.f;
    if (src) {
        int c0 = q * 128;
#pragma unroll 8
        for (int c = c0; c < c0 + 128; c += 4) {
            float4 w = *(const float4*)(src + c);
            s0 = fmaf(w.x, H[(c + 0) * 32 + j], s0);
            s1 = fmaf(w.y, H[(c + 1) * 32 + j], s1);
            s2 = fmaf(w.z, H[(c + 2) * 32 + j], s2);
            s3 = fmaf(w.w, H[(c + 3) * 32 + j], s3);
        }
    }
    part[wid][j] = (s0 + s1) + (s2 + s3);
    __syncthreads();
    if ((wid & 3) == 0) {
        float s = part[wid][j] + part[wid + 1][j] + part[wid + 2][j] + part[wid + 3][j];
        if (row < HALF) M[row * 32 + j] = s;
        else if (row == HALF) pb[j] = s;
    }
}

// hash from raw x (exact fp32): one warp per token, 4-way ILP
__global__ __launch_bounds__(256)
void hash_kernel(const float* __restrict__ x, const float* __restrict__ M,
                 const float* __restrict__ pb, int* __restrict__ hashes)
{
    int warp = (blockIdx.x * blockDim.x + threadIdx.x) >> 5;
    int lane = threadIdx.x & 31;
    if (warp >= NTOK) return;
    const float* row = x + (size_t)warp * DMODEL + HALF;
    float s0 = pb[lane], s1 = 0.f, s2 = 0.f, s3 = 0.f;
#pragma unroll 4
    for (int k = 0; k < HALF; k += 4) {
        float4 q = *(const float4*)(row + k);
        s0 = fmaf(q.x, M[(k + 0) * 32 + lane], s0);
        s1 = fmaf(q.y, M[(k + 1) * 32 + lane], s1);
        s2 = fmaf(q.z, M[(k + 2) * 32 + lane], s2);
        s3 = fmaf(q.w, M[(k + 3) * 32 + lane], s3);
    }
    float s = (s0 + s1) + (s2 + s3);
    float val; int idx;
    if (s >= -s) { val = s; idx = lane; }
    else         { val = -s; idx = lane + 32; }
#pragma unroll
    for (int off = 16; off; off >>= 1) {
        float ov = __shfl_down_sync(0xffffffffu, val, off);
        int   oi = __shfl_down_sync(0xffffffffu, idx, off);
        if (ov > val || (ov == val && oi < idx)) { val = ov; idx = oi; }
    }
    if (lane == 0) hashes[warp] = idx;
}

// ---- parallel stable counting sort (2-phase) ----
__global__ __launch_bounds__(128)
void sort1_kernel(const int* __restrict__ hashes, int* __restrict__ rank,
                  int* __restrict__ cnt)
{
    __shared__ int sh[128];
    __shared__ int hist[NBUCKETS];
    int b = blockIdx.x >> 5, ch = blockIdx.x & 31;
    int t = threadIdx.x;
    if (t < NBUCKETS) hist[t] = 0;
    int h = hashes[b * N_SEQ + ch * 128 + t];
    sh[t] = h;
    __syncthreads();
    int r = 0;
    for (int j = 0; j < t; j++) r += (sh[j] == h);
    atomicAdd(&hist[h], 1);
    rank[b * N_SEQ + ch * 128 + t] = r;
    __syncthreads();
    if (t < NBUCKETS) cnt[(b * NBUCKETS + t) * 32 + ch] = hist[t];
}

__global__ __launch_bounds__(1024)
void sort2_kernel(const int* __restrict__ hashes, const int* __restrict__ rank,
                  const int* __restrict__ cnt, int* __restrict__ idx)
{
    __shared__ int off[2048];
    __shared__ int wsum[32];
    int b = blockIdx.x, t = threadIdx.x;
    int lane = t & 31, wid = t >> 5;
    int v0 = cnt[b * 2048 + 2 * t];
    int v1 = cnt[b * 2048 + 2 * t + 1];
    int s = v0 + v1;
    int p = s;
#pragma unroll
    for (int o = 1; o < 32; o <<= 1) {
        int n = __shfl_up_sync(0xffffffffu, p, o);
        if (lane >= o) p += n;
    }
    if (lane == 31) wsum[wid] = p;
    __syncthreads();
    if (wid == 0) {
        int ws = wsum[lane];
#pragma unroll
        for (int o = 1; o < 32; o <<= 1) {
            int n = __shfl_up_sync(0xffffffffu, ws, o);
            if (lane >= o) ws += n;
        }
        wsum[lane] = ws;
    }
    __syncthreads();
    int excl = p - s + (wid ? wsum[wid - 1] : 0);
    off[2 * t] = excl;
    off[2 * t + 1] = excl + v0;
    __syncthreads();
    int* outp = idx + b * N_SEQ;
    const int* hp = hashes + b * N_SEQ;
    const int* rp = rank + b * N_SEQ;
#pragma unroll
    for (int q = 0; q < 4; q++) {
        int i = q * 1024 + t;
        int h = hp[i];
        int r = rp[i];
        int ch = i >> 7;
        outp[off[h * 32 + ch] + r] = i;
    }
}

// residual + LayerNorm; res is half. Optional extra half copy.
__global__ __launch_bounds__(256)
void ln_kernel(const float* __restrict__ x, int xoff,
               const __half* __restrict__ res,
               const float* __restrict__ g, const float* __restrict__ bta,
               float* __restrict__ out, int ooff,
               __half* __restrict__ extra)
{
    __shared__ float red[16];
    int t = blockIdx.x;
    int c0 = threadIdx.x, c1 = threadIdx.x + 256;
    float v0 = x[(size_t)t * DMODEL + xoff + c0] + __half2float(res[(size_t)t * HALF + c0]);
    float v1 = x[(size_t)t * DMODEL + xoff + c1] + __half2float(res[(size_t)t * HALF + c1]);
    float s = v0 + v1, sq = v0 * v0 + v1 * v1;
    int lane = threadIdx.x & 31, wid = threadIdx.x >> 5;
#pragma unroll
    for (int o = 16; o; o >>= 1) {
        s  += __shfl_down_sync(0xffffffffu, s, o);
        sq += __shfl_down_sync(0xffffffffu, sq, o);
    }
    if (lane == 0) { red[wid] = s; red[8 + wid] = sq; }
    __syncthreads();
    if (threadIdx.x < 32) {
        float ss = (lane < 8) ? red[lane] : 0.f;
        float qq = (lane < 8) ? red[8 + lane] : 0.f;
#pragma unroll
        for (int o = 4; o; o >>= 1) {
            ss += __shfl_down_sync(0xffffffffu, ss, o);
            qq += __shfl_down_sync(0xffffffffu, qq, o);
        }
        if (lane == 0) { red[0] = ss; red[8] = qq; }
    }
    __syncthreads();
    float mu = red[0] * (1.f / HALF);
    float var = red[8] * (1.f / HALF) - mu * mu;
    float inv = rsqrtf(var + LN_EPS);
    float o0 = (v0 - mu) * inv * g[c0] + bta[c0];
    float o1 = (v1 - mu) * inv * g[c1] + bta[c1];
    out[(size_t)t * DMODEL + ooff + c0] = o0;
    out[(size_t)t * DMODEL + ooff + c1] = o1;
    if (extra) {
        extra[(size_t)t * HALF + c0] = __float2half_rn(o0);
        extra[(size_t)t * HALF + c1] = __float2half_rn(o1);
    }
}

// ---------------------------------------------------------------------------
extern "C" void kernel_launch(void* const* d_in, const int* in_sizes, int n_in,
                              void* d_out, int out_size)
{
    const float* x       = (const float*)d_in[0];
    const float* Wqk_w   = (const float*)d_in[1];
    const float* Wqk_b   = (const float*)d_in[2];
    const float* Wv_w    = (const float*)d_in[3];
    const float* Wv_b    = (const float*)d_in[4];
    const float* unify_w = (const float*)d_in[5];
    const float* unify_b = (const float*)d_in[6];
    const float* H       = (const float*)d_in[7];
    const float* ln1_g   = (const float*)d_in[8];
    const float* ln1_b   = (const float*)d_in[9];
    const float* ff1_w   = (const float*)d_in[10];
    const float* ff1_b   = (const float*)d_in[11];
    const float* ff2_w   = (const float*)d_in[12];
    const float* ff2_b   = (const float*)d_in[13];
    const float* ln2_g   = (const float*)d_in[14];
    const float* ln2_b   = (const float*)d_in[15];
    float* out = (float*)d_out;

    __half *qkvh, *attnh, *x2h, *y1h, *hb, *uh, *fh, *WTh, *uTh, *ff1Th, *ff2Th;
    float *bqkv, *Mm, *pb;
    int *hashp, *rankp, *cntp, *idxp;
    cudaGetSymbolAddress((void**)&qkvh, g_qkvh);
    cudaGetSymbolAddress((void**)&attnh,g_attnh);
    cudaGetSymbolAddress((void**)&x2h,  g_x2h);
    cudaGetSymbolAddress((void**)&y1h,  g_y1h);
    cudaGetSymbolAddress((void**)&hb,   g_hb);
    cudaGetSymbolAddress((void**)&uh,   g_uh);
    cudaGetSymbolAddress((void**)&fh,   g_fh);
    cudaGetSymbolAddress((void**)&WTh,  g_WTh);
    cudaGetSymbolAddress((void**)&uTh,  g_uTh);
    cudaGetSymbolAddress((void**)&ff1Th,g_ff1Th);
    cudaGetSymbolAddress((void**)&ff2Th,g_ff2Th);
    cudaGetSymbolAddress((void**)&bqkv, g_bqkv);
    cudaGetSymbolAddress((void**)&Mm,   g_M);
    cudaGetSymbolAddress((void**)&pb,   g_pb);
    cudaGetSymbolAddress((void**)&hashp,g_hash);
    cudaGetSymbolAddress((void**)&rankp,g_rank);
    cudaGetSymbolAddress((void**)&cntp, g_cnt);
    cudaGetSymbolAddress((void**)&idxp, g_idx);

    cudaFuncSetAttribute(gemm_mma<0,1>, cudaFuncAttributeMaxDynamicSharedMemorySize, GK_SMEM);
    cudaFuncSetAttribute(gemm_mma<1,1>, cudaFuncAttributeMaxDynamicSharedMemorySize, GK_SMEM);
    cudaFuncSetAttribute(attn_mma, cudaFuncAttributeMaxDynamicSharedMemorySize, AT_SMEM);

    // side stream (created per call; no frees, no device allocations)
    cudaStream_t s1;
    cudaStreamCreateWithFlags(&s1, cudaStreamNonBlocking);
    cudaEvent_t evF, evJ;
    cudaEventCreateWithFlags(&evF, cudaEventDisableTiming);
    cudaEventCreateWithFlags(&evJ, cudaEventDisableTiming);

    cudaEventRecord(evF, 0);
    cudaStreamWaitEvent(s1, evF, 0);

    // side stream: hash chain first, then the remaining weight transposes
    hashM_kernel<<<257, 256, 0, s1>>>(Wqk_w, Wqk_b, H, Mm, pb);
    hash_kernel<<<NTOK / 8, 256, 0, s1>>>(x, Mm, pb, hashp);
    sort1_kernel<<<D_BATCH * 32, 128, 0, s1>>>(hashp, rankp, cntp);
    sort2_kernel<<<D_BATCH, 1024, 0, s1>>>(hashp, rankp, cntp, idxp);
    transpose_some<<<2304, 256, 0, s1>>>(512, Wqk_w, WTh, Wv_w, WTh + 512 * 512,
                                         unify_w, uTh, ff1_w, ff1Th, ff2_w, ff2Th);
    cudaEventRecord(evJ, s1);

    // main stream: prep needed by qk|v GEMM only
    cvt_x2_kernel<<<NTOK * 128 / 256, 256>>>(x, x2h);
    transpose_some<<<512, 256>>>(0, Wqk_w, WTh, Wv_w, WTh + 512 * 512,
                                 unify_w, uTh, ff1_w, ff1Th, ff2_w, ff2Th);
    bias_cat_kernel<<<4, 256>>>(Wqk_b, Wv_b, bqkv);
    gemm_mma<0,1><<<dim3(NTOK / 128, 1024 / 128), 128, GK_SMEM>>>(
        x2h, HALF, WTh, bqkv, qkvh, 1024, HALF);

    // join: attention needs qkv (stream 0) + idx (s1); unify needs uTh (s1)
    cudaStreamWaitEvent(0, evJ, 0);

    attn_mma<<<NCHUNKS, 256, AT_SMEM>>>(qkvh, idxp, attnh);

    gemm_mma<0,1><<<dim3(NTOK / 128, HALF / 128), 128, GK_SMEM>>>(
        attnh, HDV, uTh, unify_b, uh, HALF, HDV);

    ln_kernel<<<NTOK, 256>>>(x, 0, uh, ln1_g, ln1_b, out, 0, y1h);

    gemm_mma<1,1><<<dim3(NTOK / 128, FF_DIM / 128), 128, GK_SMEM>>>(
        y1h, HALF, ff1Th, ff1_b, hb, FF_DIM, HALF);
    gemm_mma<0,1><<<dim3(NTOK / 128, HALF / 128), 128, GK_SMEM>>>(
        hb, FF_DIM, ff2Th, ff2_b, fh, HALF, FF_DIM);

    ln_kernel<<<NTOK, 256>>>(x, HALF, fh, ln2_g, ln2_b, out, HALF, nullptr);
}